// round 1
// baseline (speedup 1.0000x reference)
#include <cuda_runtime.h>
#include <cuda_bf16.h>

#define B_  32
#define N_  300
#define H_  1024
#define W_  1024
#define HW_ (1024 * 1024)

// 128 MB scratch for the per-batch integral image of (footpath - driveway).
__device__ float g_ii[(size_t)B_ * HW_];

// ---------------------------------------------------------------------------
// Kernel 1: per-row inclusive prefix sum of diff = seg[b,2,y,:] - seg[b,1,y,:]
// One 256-thread block per row; each thread owns 4 consecutive elements (float4).
// ---------------------------------------------------------------------------
__global__ void __launch_bounds__(256) rowScan(const float* __restrict__ seg) {
    int row = blockIdx.x;          // 0 .. B*H-1
    int b = row >> 10;
    int y = row & (H_ - 1);
    int t = threadIdx.x;

    const float4* p1 = (const float4*)(seg + ((size_t)b * 3 + 1) * HW_ + (size_t)y * W_);
    const float4* p2 = (const float4*)(seg + ((size_t)b * 3 + 2) * HW_ + (size_t)y * W_);

    float4 a = p1[t];
    float4 c = p2[t];
    float d0 = c.x - a.x;
    float d1 = c.y - a.y;
    float d2 = c.z - a.z;
    float d3 = c.w - a.w;
    // per-thread inclusive prefixes
    float s1 = d0 + d1;
    float s2 = s1 + d2;
    float s3 = s2 + d3;

    // warp inclusive scan of per-thread totals
    unsigned lane = t & 31, wid = t >> 5;
    float v = s3;
    #pragma unroll
    for (int o = 1; o < 32; o <<= 1) {
        float n = __shfl_up_sync(0xFFFFFFFFu, v, o);
        if (lane >= o) v += n;
    }

    __shared__ float wsum[8];
    if (lane == 31) wsum[wid] = v;
    __syncthreads();
    if (t < 8) {
        float w = wsum[t];
        #pragma unroll
        for (int o = 1; o < 8; o <<= 1) {
            float n = __shfl_up_sync(0xFFu, w, o);
            if ((int)t >= o) w += n;
        }
        wsum[t] = w;
    }
    __syncthreads();

    float warpoff = (wid > 0) ? wsum[wid - 1] : 0.0f;
    float excl = warpoff + (v - s3);   // exclusive prefix for this thread

    float4 out;
    out.x = excl + d0;
    out.y = excl + s1;
    out.z = excl + s2;
    out.w = excl + s3;
    ((float4*)(g_ii + (size_t)b * HW_ + (size_t)y * W_))[t] = out;
}

// ---------------------------------------------------------------------------
// Kernel 2: in-place column prefix sum (turns row-prefix into full integral img).
// One thread per column; sequential walk down 1024 rows, unrolled x8 for MLP.
// ---------------------------------------------------------------------------
__global__ void __launch_bounds__(256) colScan() {
    int b = blockIdx.y;
    int x = blockIdx.x * blockDim.x + threadIdx.x;  // 0..1023
    float* p = g_ii + (size_t)b * HW_ + x;

    float acc = 0.0f;
    for (int y = 0; y < H_; y += 8) {
        float v0 = p[(size_t)(y + 0) * W_];
        float v1 = p[(size_t)(y + 1) * W_];
        float v2 = p[(size_t)(y + 2) * W_];
        float v3 = p[(size_t)(y + 3) * W_];
        float v4 = p[(size_t)(y + 4) * W_];
        float v5 = p[(size_t)(y + 5) * W_];
        float v6 = p[(size_t)(y + 6) * W_];
        float v7 = p[(size_t)(y + 7) * W_];
        acc += v0; p[(size_t)(y + 0) * W_] = acc;
        acc += v1; p[(size_t)(y + 1) * W_] = acc;
        acc += v2; p[(size_t)(y + 2) * W_] = acc;
        acc += v3; p[(size_t)(y + 3) * W_] = acc;
        acc += v4; p[(size_t)(y + 4) * W_] = acc;
        acc += v5; p[(size_t)(y + 5) * W_] = acc;
        acc += v6; p[(size_t)(y + 6) * W_] = acc;
        acc += v7; p[(size_t)(y + 7) * W_] = acc;
    }
}

// ---------------------------------------------------------------------------
// Kernel 3: per-box gather + masked reduction. Single block, no atomics.
// ---------------------------------------------------------------------------
__device__ __forceinline__ int to_idx(float v, int m) {
    int i = (int)v;                 // trunc toward zero, matches jnp.trunc+int32
    if (i < 0) i = 0;
    if (i > m - 1) i = m - 1;
    return i;
}

__global__ void __launch_bounds__(1024) boxKernel(const float* __restrict__ boxes,
                                                  const float* __restrict__ conf,
                                                  float* __restrict__ out) {
    int t = threadIdx.x;
    double acc = 0.0;

    for (int i = t; i < B_ * N_; i += 1024) {
        int b = i / N_;
        const float* bx = boxes + (size_t)i * 4;
        float cx = bx[0], cy = bx[1], w = bx[2], h = bx[3];
        float cf = conf[i];

        int x1 = to_idx((cx - 0.5f * w) * (float)W_, W_);
        int x2 = to_idx((cx + 0.5f * w) * (float)W_, W_);
        int y1 = to_idx((cy - 0.5f * h) * (float)H_, H_);
        int y2 = to_idx((cy + 0.5f * h) * (float)H_, H_);

        bool valid = (cf >= 0.3f) && (x2 > x1) && (y2 > y1);
        if (valid) {
            float area = (float)((y2 - y1) * (x2 - x1));
            const float* P = g_ii + (size_t)b * HW_;
            // padded-ii corner: sum over rows < y, cols < x
            auto g = [&](int yy, int xx) -> float {
                return (yy > 0 && xx > 0) ? P[(size_t)(yy - 1) * W_ + (xx - 1)] : 0.0f;
            };
            float s = g(y2, x2) - g(y1, x2) - g(y2, x1) + g(y1, x1);
            float pb = fmaxf(s / area, 0.0f) * cf;
            acc += (double)pb;
        }
    }

    // block reduction in double
    __shared__ double sh[32];
    unsigned lane = t & 31, wid = t >> 5;
    #pragma unroll
    for (int o = 16; o > 0; o >>= 1)
        acc += __shfl_down_sync(0xFFFFFFFFu, acc, o);
    if (lane == 0) sh[wid] = acc;
    __syncthreads();
    if (wid == 0) {
        double v = (lane < 32) ? sh[lane] : 0.0;
        #pragma unroll
        for (int o = 16; o > 0; o >>= 1)
            v += __shfl_down_sync(0xFFFFFFFFu, v, o);
        if (lane == 0) out[0] = (float)(v / (double)(B_ * N_));
    }
}

// ---------------------------------------------------------------------------
extern "C" void kernel_launch(void* const* d_in, const int* in_sizes, int n_in,
                              void* d_out, int out_size) {
    const float* det_boxes = (const float*)d_in[0];       // (32,300,4)
    const float* det_conf  = (const float*)d_in[1];       // (32,300)
    const float* seg_masks = (const float*)d_in[2];       // (32,3,1024,1024)
    float* out = (float*)d_out;

    rowScan<<<B_ * H_, 256>>>(seg_masks);
    dim3 g2(W_ / 256, B_);
    colScan<<<g2, 256>>>();
    boxKernel<<<1, 1024>>>(det_boxes, det_conf, out);
}

// round 3
// speedup vs baseline: 1.3853x; 1.3853x over previous
#include <cuda_runtime.h>
#include <cuda_bf16.h>

#define B_   32
#define N_   300
#define H_   1024
#define W_   1024
#define HW_  (1024 * 1024)
#define NCHUNK   128                 // row-chunks per batch (8 rows each)
#define TOTCHUNK (B_ * NCHUNK)       // 4096
#define SLOTS    96                  // bucket capacity (Poisson mean 9.4; P(>=96) ~ 0)
#define NQ       (B_ * N_ * 4)       // 38400 corner slots

// Scratch (static device arrays — no allocation).
__device__ float g_agg[(size_t)TOTCHUNK * W_];   // 16 MB: chunk column aggregates -> exclusive prefix
__device__ float g_corner[NQ];                   // chunk-local corner values
__device__ int   g_cnt[TOTCHUNK];
__device__ int   g_bucket[TOTCHUNK * SLOTS];

__device__ __forceinline__ int to_idx(float v, int m) {
    int i = (int)v;                  // trunc toward zero == jnp.trunc -> int32
    if (i < 0) i = 0;
    if (i > m - 1) i = m - 1;
    return i;
}

// ---------------------------------------------------------------------------
// K0: reset bucket counters (must run each graph replay).
// ---------------------------------------------------------------------------
__global__ void initKernel() {
    int i = blockIdx.x * blockDim.x + threadIdx.x;
    if (i < TOTCHUNK) g_cnt[i] = 0;
}

// ---------------------------------------------------------------------------
// K1: bucket corner queries by (batch, row-chunk). One thread per box.
// Packed entry: qid[0:17) | x[17:27) | r[27:30)
// ---------------------------------------------------------------------------
__global__ void bucketKernel(const float* __restrict__ boxes,
                             const float* __restrict__ conf) {
    int i = blockIdx.x * blockDim.x + threadIdx.x;
    if (i >= B_ * N_) return;
    int b = i / N_;
    float cx = boxes[4 * i + 0], cy = boxes[4 * i + 1];
    float w  = boxes[4 * i + 2], h  = boxes[4 * i + 3];
    float cf = conf[i];

    int x1 = to_idx((cx - 0.5f * w) * (float)W_, W_);
    int x2 = to_idx((cx + 0.5f * w) * (float)W_, W_);
    int y1 = to_idx((cy - 0.5f * h) * (float)H_, H_);
    int y2 = to_idx((cy + 0.5f * h) * (float)H_, H_);
    if (!(cf >= 0.3f && x2 > x1 && y2 > y1)) return;

    int ys[4] = {y2, y1, y2, y1};
    int xs[4] = {x2, x2, x1, x1};
    #pragma unroll
    for (int k = 0; k < 4; k++) {
        int yy = ys[k], xx = xs[k];
        if (yy > 0 && xx > 0) {
            int r = (yy - 1) & 7;
            int c = (yy - 1) >> 3;
            int chunk = b * NCHUNK + c;
            int x = xx - 1;
            int slot = atomicAdd(&g_cnt[chunk], 1);
            if (slot < SLOTS)
                g_bucket[chunk * SLOTS + slot] = (4 * i + k) | (x << 17) | (r << 27);
        }
    }
}

// ---------------------------------------------------------------------------
// K2: per-chunk 2D local prefix. One block = one (b, 8-row chunk).
//  - warp w row-scans row w (diff of classes 2-1) into smem
//  - column pass: thread t owns cols 4t..4t+3, local column prefix in smem,
//    aggregate -> g_agg
//  - answer this chunk's corner queries with the LOCAL ii value
// ---------------------------------------------------------------------------
__global__ void __launch_bounds__(256) scanChunk(const float* __restrict__ seg) {
    __shared__ float sm[8 * W_];     // 32 KB
    int chunk = blockIdx.x;
    int b = chunk >> 7;
    int c = chunk & (NCHUNK - 1);
    int t = threadIdx.x;
    int lane = t & 31, wrow = t >> 5;
    int y = c * 8 + wrow;

    const float* p1 = seg + ((size_t)b * 3 + 1) * HW_ + (size_t)y * W_;
    const float* p2 = seg + ((size_t)b * 3 + 2) * HW_ + (size_t)y * W_;

    // preload diff for the whole row segment-wise (8 x float4 per thread)
    float4 d[8];
    #pragma unroll
    for (int i = 0; i < 8; i++) {
        int col = i * 128 + lane * 4;
        float4 a  = *(const float4*)(p1 + col);
        float4 bb = *(const float4*)(p2 + col);
        d[i] = make_float4(bb.x - a.x, bb.y - a.y, bb.z - a.z, bb.w - a.w);
    }

    // warp-sequential inclusive row scan (8 segments of 128)
    float carry = 0.0f;
    #pragma unroll
    for (int i = 0; i < 8; i++) {
        float4 v = d[i];
        float s1 = v.x + v.y, s2 = s1 + v.z, s3 = s2 + v.w;
        float tot = s3;
        #pragma unroll
        for (int o = 1; o < 32; o <<= 1) {
            float n = __shfl_up_sync(0xFFFFFFFFu, tot, o);
            if (lane >= o) tot += n;
        }
        float excl = carry + (tot - s3);
        *(float4*)(&sm[wrow * W_ + i * 128 + lane * 4]) =
            make_float4(excl + v.x, excl + s1, excl + s2, excl + s3);
        carry += __shfl_sync(0xFFFFFFFFu, tot, 31);
    }
    __syncthreads();

    // column-local inclusive prefix over the 8 rows; thread owns 4 columns
    int x0 = t * 4;
    float4 acc = make_float4(0.f, 0.f, 0.f, 0.f);
    #pragma unroll
    for (int r = 0; r < 8; r++) {
        float4 v = *(float4*)(&sm[r * W_ + x0]);
        acc.x += v.x; acc.y += v.y; acc.z += v.z; acc.w += v.w;
        *(float4*)(&sm[r * W_ + x0]) = acc;       // L[r][x]
    }
    *(float4*)(&g_agg[(size_t)chunk * W_ + x0]) = acc;   // chunk aggregate
    __syncthreads();

    // answer this chunk's queries with the local value
    int cnt = g_cnt[chunk];
    if (cnt > SLOTS) cnt = SLOTS;
    for (int q = t; q < cnt; q += 256) {
        int e   = g_bucket[chunk * SLOTS + q];
        int qid = e & 0x1FFFF;
        int x   = (e >> 17) & 0x3FF;
        int r   = (e >> 27) & 7;
        g_corner[qid] = sm[r * W_ + x];
    }
}

// ---------------------------------------------------------------------------
// K2b: in-place exclusive prefix of g_agg over the 128 chunks of each batch,
// per column. Fixed sequential order => deterministic. One thread per column.
// ---------------------------------------------------------------------------
__global__ void __launch_bounds__(256) chunkScan() {
    int i = blockIdx.x * blockDim.x + threadIdx.x;   // 0 .. 32767
    int b = i >> 10;
    int x = i & (W_ - 1);
    float* p = g_agg + (size_t)b * NCHUNK * W_ + x;
    float E = 0.0f;
    #pragma unroll 8
    for (int c = 0; c < NCHUNK; c++) {
        float v = p[(size_t)c * W_];
        p[(size_t)c * W_] = E;
        E += v;
    }
}

// ---------------------------------------------------------------------------
// K3: per-box combine + masked mean. Single block, fixed-order double reduce.
// ---------------------------------------------------------------------------
__global__ void __launch_bounds__(1024) boxKernel(const float* __restrict__ boxes,
                                                  const float* __restrict__ conf,
                                                  float* __restrict__ out) {
    int t = threadIdx.x;
    double acc = 0.0;

    for (int i = t; i < B_ * N_; i += 1024) {
        int b = i / N_;
        float cx = boxes[4 * i + 0], cy = boxes[4 * i + 1];
        float w  = boxes[4 * i + 2], h  = boxes[4 * i + 3];
        float cf = conf[i];

        int x1 = to_idx((cx - 0.5f * w) * (float)W_, W_);
        int x2 = to_idx((cx + 0.5f * w) * (float)W_, W_);
        int y1 = to_idx((cy - 0.5f * h) * (float)H_, H_);
        int y2 = to_idx((cy + 0.5f * h) * (float)H_, H_);

        if (cf >= 0.3f && x2 > x1 && y2 > y1) {
            float area = (float)((y2 - y1) * (x2 - x1));
            int ys[4] = {y2, y1, y2, y1};
            int xs[4] = {x2, x2, x1, x1};
            const float sg[4] = {1.f, -1.f, -1.f, 1.f};
            float s = 0.0f;
            #pragma unroll
            for (int k = 0; k < 4; k++) {
                int yy = ys[k], xx = xs[k];
                if (yy > 0 && xx > 0) {
                    int c = (yy - 1) >> 3;
                    int x = xx - 1;
                    float v = g_corner[4 * i + k]
                            + g_agg[((size_t)(b * NCHUNK + c)) * W_ + x];
                    s += sg[k] * v;
                }
            }
            acc += (double)(fmaxf(s / area, 0.0f) * cf);
        }
    }

    __shared__ double sh[32];
    unsigned lane = t & 31, wid = t >> 5;
    #pragma unroll
    for (int o = 16; o > 0; o >>= 1)
        acc += __shfl_down_sync(0xFFFFFFFFu, acc, o);
    if (lane == 0) sh[wid] = acc;
    __syncthreads();
    if (wid == 0) {
        double v = sh[lane];
        #pragma unroll
        for (int o = 16; o > 0; o >>= 1)
            v += __shfl_down_sync(0xFFFFFFFFu, v, o);
        if (lane == 0) out[0] = (float)(v / (double)(B_ * N_));
    }
}

// ---------------------------------------------------------------------------
extern "C" void kernel_launch(void* const* d_in, const int* in_sizes, int n_in,
                              void* d_out, int out_size) {
    const float* det_boxes = (const float*)d_in[0];   // (32,300,4)
    const float* det_conf  = (const float*)d_in[1];   // (32,300)
    const float* seg_masks = (const float*)d_in[2];   // (32,3,1024,1024)
    float* out = (float*)d_out;

    initKernel<<<(TOTCHUNK + 255) / 256, 256>>>();
    bucketKernel<<<(B_ * N_ + 255) / 256, 256>>>(det_boxes, det_conf);
    scanChunk<<<TOTCHUNK, 256>>>(seg_masks);
    chunkScan<<<(B_ * W_) / 256, 256>>>();
    boxKernel<<<1, 1024>>>(det_boxes, det_conf, out);
}

// round 7
// speedup vs baseline: 1.8210x; 1.3145x over previous
#include <cuda_runtime.h>
#include <cuda_bf16.h>

#define B_   32
#define N_   300
#define H_   1024
#define W_   1024
#define HW_  (1024 * 1024)
#define NCHUNK   128                 // row-chunks per batch (8 rows each)
#define TOTCHUNK (B_ * NCHUNK)       // 4096
#define SLOTS    256                 // clamped corners pile up in edge chunks (~108 mean); 256 is safe
#define NQ       (B_ * N_ * 4)       // 38400 corner slots

// Scratch (static device arrays — no allocation).
__device__ float g_agg[(size_t)TOTCHUNK * W_];   // 16 MB: chunk column aggregates -> exclusive prefix
__device__ float g_corner[NQ];                   // chunk-local corner values
__device__ int   g_cnt[TOTCHUNK];
__device__ int   g_bucket[TOTCHUNK * SLOTS];

__device__ __forceinline__ int to_idx(float v, int m) {
    int i = (int)v;                  // trunc toward zero == jnp.trunc -> int32
    if (i < 0) i = 0;
    if (i > m - 1) i = m - 1;
    return i;
}

// ---------------------------------------------------------------------------
// K0: reset bucket counters (must run each graph replay).
// ---------------------------------------------------------------------------
__global__ void initKernel() {
    int i = blockIdx.x * blockDim.x + threadIdx.x;
    if (i < TOTCHUNK) g_cnt[i] = 0;
}

// ---------------------------------------------------------------------------
// K1: bucket corner queries by (batch, row-chunk). One thread per box.
// Packed entry: qid[0:17) | x[17:27) | r[27:30)
// ---------------------------------------------------------------------------
__global__ void bucketKernel(const float* __restrict__ boxes,
                             const float* __restrict__ conf) {
    int i = blockIdx.x * blockDim.x + threadIdx.x;
    if (i >= B_ * N_) return;
    int b = i / N_;
    float cx = boxes[4 * i + 0], cy = boxes[4 * i + 1];
    float w  = boxes[4 * i + 2], h  = boxes[4 * i + 3];
    float cf = conf[i];

    int x1 = to_idx((cx - 0.5f * w) * (float)W_, W_);
    int x2 = to_idx((cx + 0.5f * w) * (float)W_, W_);
    int y1 = to_idx((cy - 0.5f * h) * (float)H_, H_);
    int y2 = to_idx((cy + 0.5f * h) * (float)H_, H_);
    if (!(cf >= 0.3f && x2 > x1 && y2 > y1)) return;

    int ys[4] = {y2, y1, y2, y1};
    int xs[4] = {x2, x2, x1, x1};
    #pragma unroll
    for (int k = 0; k < 4; k++) {
        int yy = ys[k], xx = xs[k];
        if (yy > 0 && xx > 0) {
            int r = (yy - 1) & 7;
            int c = (yy - 1) >> 3;
            int chunk = b * NCHUNK + c;
            int x = xx - 1;
            int slot = atomicAdd(&g_cnt[chunk], 1);
            if (slot < SLOTS)
                g_bucket[chunk * SLOTS + slot] = (4 * i + k) | (x << 17) | (r << 27);
        }
    }
}

// ---------------------------------------------------------------------------
// K2: per-chunk 2D local prefix. One block = one (b, 8-row chunk).
// ---------------------------------------------------------------------------
__global__ void __launch_bounds__(256) scanChunk(const float* __restrict__ seg) {
    __shared__ float sm[8 * W_];     // 32 KB
    int chunk = blockIdx.x;
    int b = chunk >> 7;
    int c = chunk & (NCHUNK - 1);
    int t = threadIdx.x;
    int lane = t & 31, wrow = t >> 5;
    int y = c * 8 + wrow;

    const float* p1 = seg + ((size_t)b * 3 + 1) * HW_ + (size_t)y * W_;
    const float* p2 = seg + ((size_t)b * 3 + 2) * HW_ + (size_t)y * W_;

    // preload diff for the whole row segment-wise (8 x float4 per thread)
    float4 d[8];
    #pragma unroll
    for (int i = 0; i < 8; i++) {
        int col = i * 128 + lane * 4;
        float4 a  = *(const float4*)(p1 + col);
        float4 bb = *(const float4*)(p2 + col);
        d[i] = make_float4(bb.x - a.x, bb.y - a.y, bb.z - a.z, bb.w - a.w);
    }

    // warp-sequential inclusive row scan (8 segments of 128)
    float carry = 0.0f;
    #pragma unroll
    for (int i = 0; i < 8; i++) {
        float4 v = d[i];
        float s1 = v.x + v.y, s2 = s1 + v.z, s3 = s2 + v.w;
        float tot = s3;
        #pragma unroll
        for (int o = 1; o < 32; o <<= 1) {
            float n = __shfl_up_sync(0xFFFFFFFFu, tot, o);
            if (lane >= o) tot += n;
        }
        float excl = carry + (tot - s3);
        *(float4*)(&sm[wrow * W_ + i * 128 + lane * 4]) =
            make_float4(excl + v.x, excl + s1, excl + s2, excl + s3);
        carry += __shfl_sync(0xFFFFFFFFu, tot, 31);
    }
    __syncthreads();

    // column-local inclusive prefix over the 8 rows; thread owns 4 columns
    int x0 = t * 4;
    float4 acc = make_float4(0.f, 0.f, 0.f, 0.f);
    #pragma unroll
    for (int r = 0; r < 8; r++) {
        float4 v = *(float4*)(&sm[r * W_ + x0]);
        acc.x += v.x; acc.y += v.y; acc.z += v.z; acc.w += v.w;
        *(float4*)(&sm[r * W_ + x0]) = acc;       // L[r][x]
    }
    *(float4*)(&g_agg[(size_t)chunk * W_ + x0]) = acc;   // chunk aggregate
    __syncthreads();

    // answer this chunk's queries with the local value
    int cnt = g_cnt[chunk];
    if (cnt > SLOTS) cnt = SLOTS;
    for (int q = t; q < cnt; q += 256) {
        int e   = g_bucket[chunk * SLOTS + q];
        int qid = e & 0x1FFFF;
        int x   = (e >> 17) & 0x3FF;
        int r   = (e >> 27) & 7;
        g_corner[qid] = sm[r * W_ + x];
    }
}

// ---------------------------------------------------------------------------
// K2b: in-place exclusive prefix of g_agg over 128 chunks per (b, column).
// Re-tiled for parallelism: 1024 blocks; each warp handles 32 consecutive
// columns for one 16-chunk segment (16 independent loads -> MLP=16), then a
// cross-segment smem scan. Per-column order is fixed => deterministic.
// ---------------------------------------------------------------------------
__global__ void __launch_bounds__(256) chunkScan() {
    __shared__ float sums[8][32];
    int blk  = blockIdx.x;            // 0..1023
    int b    = blk >> 5;              // batch
    int xg   = blk & 31;              // 32-column group
    int lane = threadIdx.x & 31;
    int seg  = threadIdx.x >> 5;      // 16-chunk segment 0..7
    int x    = xg * 32 + lane;

    float* base = g_agg + (size_t)b * NCHUNK * W_ + x;

    float v[16];
    #pragma unroll
    for (int j = 0; j < 16; j++)
        v[j] = base[(size_t)(seg * 16 + j) * W_];

    float tot = 0.0f;
    #pragma unroll
    for (int j = 0; j < 16; j++) tot += v[j];

    sums[seg][lane] = tot;
    __syncthreads();

    float E = 0.0f;
    #pragma unroll
    for (int s = 0; s < 8; s++)
        if (s < seg) E += sums[s][lane];

    #pragma unroll
    for (int j = 0; j < 16; j++) {
        float tv = v[j];
        base[(size_t)(seg * 16 + j) * W_] = E;   // exclusive prefix
        E += tv;
    }
}

// ---------------------------------------------------------------------------
// K3: per-box combine + masked mean. Single block, fixed-order double reduce.
// ---------------------------------------------------------------------------
__global__ void __launch_bounds__(1024) boxKernel(const float* __restrict__ boxes,
                                                  const float* __restrict__ conf,
                                                  float* __restrict__ out) {
    int t = threadIdx.x;
    double acc = 0.0;

    for (int i = t; i < B_ * N_; i += 1024) {
        int b = i / N_;
        float cx = boxes[4 * i + 0], cy = boxes[4 * i + 1];
        float w  = boxes[4 * i + 2], h  = boxes[4 * i + 3];
        float cf = conf[i];

        int x1 = to_idx((cx - 0.5f * w) * (float)W_, W_);
        int x2 = to_idx((cx + 0.5f * w) * (float)W_, W_);
        int y1 = to_idx((cy - 0.5f * h) * (float)H_, H_);
        int y2 = to_idx((cy + 0.5f * h) * (float)H_, H_);

        if (cf >= 0.3f && x2 > x1 && y2 > y1) {
            float area = (float)((y2 - y1) * (x2 - x1));
            int ys[4] = {y2, y1, y2, y1};
            int xs[4] = {x2, x2, x1, x1};
            const float sg[4] = {1.f, -1.f, -1.f, 1.f};
            float s = 0.0f;
            #pragma unroll
            for (int k = 0; k < 4; k++) {
                int yy = ys[k], xx = xs[k];
                if (yy > 0 && xx > 0) {
                    int c = (yy - 1) >> 3;
                    int x = xx - 1;
                    float v = g_corner[4 * i + k]
                            + g_agg[((size_t)(b * NCHUNK + c)) * W_ + x];
                    s += sg[k] * v;
                }
            }
            acc += (double)(fmaxf(s / area, 0.0f) * cf);
        }
    }

    __shared__ double sh[32];
    unsigned lane = t & 31, wid = t >> 5;
    #pragma unroll
    for (int o = 16; o > 0; o >>= 1)
        acc += __shfl_down_sync(0xFFFFFFFFu, acc, o);
    if (lane == 0) sh[wid] = acc;
    __syncthreads();
    if (wid == 0) {
        double v = sh[lane];
        #pragma unroll
        for (int o = 16; o > 0; o >>= 1)
            v += __shfl_down_sync(0xFFFFFFFFu, v, o);
        if (lane == 0) out[0] = (float)(v / (double)(B_ * N_));
    }
}

// ---------------------------------------------------------------------------
extern "C" void kernel_launch(void* const* d_in, const int* in_sizes, int n_in,
                              void* d_out, int out_size) {
    const float* det_boxes = (const float*)d_in[0];   // (32,300,4)
    const float* det_conf  = (const float*)d_in[1];   // (32,300)
    const float* seg_masks = (const float*)d_in[2];   // (32,3,1024,1024)
    float* out = (float*)d_out;

    initKernel<<<(TOTCHUNK + 255) / 256, 256>>>();
    bucketKernel<<<(B_ * N_ + 255) / 256, 256>>>(det_boxes, det_conf);
    scanChunk<<<TOTCHUNK, 256>>>(seg_masks);
    chunkScan<<<B_ * 32, 256>>>();
    boxKernel<<<1, 1024>>>(det_boxes, det_conf, out);
}

// round 10
// speedup vs baseline: 1.8371x; 1.0089x over previous
#include <cuda_runtime.h>
#include <cuda_bf16.h>

#define B_   32
#define N_   300
#define H_   1024
#define W_   1024
#define HW_  (1024 * 1024)
#define NCHUNK   128                 // row-chunks per batch (8 rows each)
#define TOTCHUNK (B_ * NCHUNK)       // 4096
#define SLOTS    256                 // edge chunks collect ~110 clamped corners; 256 is safe
#define NQ       (B_ * N_ * 4)       // 38400 corner slots

// Scratch (static device arrays — no allocation). Zero-initialized at load.
__device__ float g_agg[(size_t)TOTCHUNK * W_];   // 16 MB: chunk column aggregates -> exclusive prefix
__device__ float g_corner[NQ];                   // chunk-local corner values
__device__ int   g_cnt[TOTCHUNK];
__device__ int   g_bucket[TOTCHUNK * SLOTS];

__device__ __forceinline__ int to_idx(float v, int m) {
    int i = (int)v;                  // trunc toward zero == jnp.trunc -> int32
    if (i < 0) i = 0;
    if (i > m - 1) i = m - 1;
    return i;
}

// ---------------------------------------------------------------------------
// K1: bucket corner queries by (batch, row-chunk). One thread per box.
// Packed entry: qid[0:17) | x[17:27) | r[27:30)
// Relies on g_cnt == 0 (zeroed at module load, and re-zeroed by boxKernel).
// ---------------------------------------------------------------------------
__global__ void bucketKernel(const float* __restrict__ boxes,
                             const float* __restrict__ conf) {
    int i = blockIdx.x * blockDim.x + threadIdx.x;
    if (i >= B_ * N_) return;
    int b = i / N_;
    float4 bx = ((const float4*)boxes)[i];
    float cx = bx.x, cy = bx.y, w = bx.z, h = bx.w;
    float cf = conf[i];

    int x1 = to_idx((cx - 0.5f * w) * (float)W_, W_);
    int x2 = to_idx((cx + 0.5f * w) * (float)W_, W_);
    int y1 = to_idx((cy - 0.5f * h) * (float)H_, H_);
    int y2 = to_idx((cy + 0.5f * h) * (float)H_, H_);
    if (!(cf >= 0.3f && x2 > x1 && y2 > y1)) return;

    int ys[4] = {y2, y1, y2, y1};
    int xs[4] = {x2, x2, x1, x1};
    #pragma unroll
    for (int k = 0; k < 4; k++) {
        int yy = ys[k], xx = xs[k];
        if (yy > 0 && xx > 0) {
            int r = (yy - 1) & 7;
            int c = (yy - 1) >> 3;
            int chunk = b * NCHUNK + c;
            int x = xx - 1;
            int slot = atomicAdd(&g_cnt[chunk], 1);
            if (slot < SLOTS)
                g_bucket[chunk * SLOTS + slot] = (4 * i + k) | (x << 17) | (r << 27);
        }
    }
}

// ---------------------------------------------------------------------------
// K2: per-chunk local prefix. One block = one (b, 8-row chunk).
//  - warp w row-scans row w (diff of classes 2-1) into smem, in two halves
//    (halves live registers -> more resident CTAs)
//  - column pass accumulates in registers only; writes chunk aggregate
//  - queries answered by summing rowprefix[0..r][x] (same add order as before)
// ---------------------------------------------------------------------------
__global__ void __launch_bounds__(256) scanChunk(const float* __restrict__ seg) {
    __shared__ float sm[8 * W_];     // 32 KB: row-wise prefix sums
    int chunk = blockIdx.x;
    int b = chunk >> 7;
    int c = chunk & (NCHUNK - 1);
    int t = threadIdx.x;
    int lane = t & 31, wrow = t >> 5;
    int y = c * 8 + wrow;

    const float* p1 = seg + ((size_t)b * 3 + 1) * HW_ + (size_t)y * W_;
    const float* p2 = seg + ((size_t)b * 3 + 2) * HW_ + (size_t)y * W_;

    float carry = 0.0f;
    #pragma unroll
    for (int half = 0; half < 2; half++) {
        // load 4 segments (streaming: data is read exactly once)
        float4 d[4];
        #pragma unroll
        for (int i = 0; i < 4; i++) {
            int col = (half * 4 + i) * 128 + lane * 4;
            float4 a  = __ldcs((const float4*)(p1 + col));
            float4 bb = __ldcs((const float4*)(p2 + col));
            d[i] = make_float4(bb.x - a.x, bb.y - a.y, bb.z - a.z, bb.w - a.w);
        }
        // warp-sequential inclusive row scan over these 4 segments of 128
        #pragma unroll
        for (int i = 0; i < 4; i++) {
            float4 v = d[i];
            float s1 = v.x + v.y, s2 = s1 + v.z, s3 = s2 + v.w;
            float tot = s3;
            #pragma unroll
            for (int o = 1; o < 32; o <<= 1) {
                float n = __shfl_up_sync(0xFFFFFFFFu, tot, o);
                if (lane >= o) tot += n;
            }
            float excl = carry + (tot - s3);
            *(float4*)(&sm[wrow * W_ + (half * 4 + i) * 128 + lane * 4]) =
                make_float4(excl + v.x, excl + s1, excl + s2, excl + s3);
            carry += __shfl_sync(0xFFFFFFFFu, tot, 31);
        }
    }
    __syncthreads();

    // column aggregate over the 8 rows; registers only, no smem write-back
    int x0 = t * 4;
    float4 acc = make_float4(0.f, 0.f, 0.f, 0.f);
    #pragma unroll
    for (int r = 0; r < 8; r++) {
        float4 v = *(float4*)(&sm[r * W_ + x0]);
        acc.x += v.x; acc.y += v.y; acc.z += v.z; acc.w += v.w;
    }
    *(float4*)(&g_agg[(size_t)chunk * W_ + x0]) = acc;

    // answer this chunk's queries: local ii(r,x) = sum_{r'<=r} rowprefix[r'][x]
    int cnt = g_cnt[chunk];
    if (cnt > SLOTS) cnt = SLOTS;
    for (int q = t; q < cnt; q += 256) {
        int e   = g_bucket[chunk * SLOTS + q];
        int qid = e & 0x1FFFF;
        int x   = (e >> 17) & 0x3FF;
        int r   = (e >> 27) & 7;
        float s = 0.0f;
        for (int rr = 0; rr <= r; rr++)      // same order as the old column acc
            s += sm[rr * W_ + x];
        g_corner[qid] = s;
    }
}

// ---------------------------------------------------------------------------
// K2b: in-place exclusive prefix of g_agg over 128 chunks per (b, column).
// 1024 blocks; warp = 32 columns x one 16-chunk segment (MLP=16), cross-
// segment smem scan. Fixed per-column order => deterministic.
// ---------------------------------------------------------------------------
__global__ void __launch_bounds__(256) chunkScan() {
    __shared__ float sums[8][32];
    int blk  = blockIdx.x;            // 0..1023
    int b    = blk >> 5;              // batch
    int xg   = blk & 31;              // 32-column group
    int lane = threadIdx.x & 31;
    int seg  = threadIdx.x >> 5;      // 16-chunk segment 0..7
    int x    = xg * 32 + lane;

    float* base = g_agg + (size_t)b * NCHUNK * W_ + x;

    float v[16];
    #pragma unroll
    for (int j = 0; j < 16; j++)
        v[j] = base[(size_t)(seg * 16 + j) * W_];

    float tot = 0.0f;
    #pragma unroll
    for (int j = 0; j < 16; j++) tot += v[j];

    sums[seg][lane] = tot;
    __syncthreads();

    float E = 0.0f;
    #pragma unroll
    for (int s = 0; s < 8; s++)
        if (s < seg) E += sums[s][lane];

    #pragma unroll
    for (int j = 0; j < 16; j++) {
        float tv = v[j];
        base[(size_t)(seg * 16 + j) * W_] = E;   // exclusive prefix
        E += tv;
    }
}

// ---------------------------------------------------------------------------
// K3: per-box combine + masked mean + reset g_cnt for the next call.
// Single block, fixed-order double reduce => deterministic.
// ---------------------------------------------------------------------------
__global__ void __launch_bounds__(1024) boxKernel(const float* __restrict__ boxes,
                                                  const float* __restrict__ conf,
                                                  float* __restrict__ out) {
    int t = threadIdx.x;

    // reset bucket counters for the next kernel_launch call (they were fully
    // consumed by bucketKernel/scanChunk earlier in THIS call)
    #pragma unroll
    for (int j = 0; j < TOTCHUNK / 1024; j++)
        g_cnt[j * 1024 + t] = 0;

    double acc = 0.0;
    for (int i = t; i < B_ * N_; i += 1024) {
        int b = i / N_;
        float4 bx = ((const float4*)boxes)[i];
        float cx = bx.x, cy = bx.y, w = bx.z, h = bx.w;
        float cf = conf[i];

        int x1 = to_idx((cx - 0.5f * w) * (float)W_, W_);
        int x2 = to_idx((cx + 0.5f * w) * (float)W_, W_);
        int y1 = to_idx((cy - 0.5f * h) * (float)H_, H_);
        int y2 = to_idx((cy + 0.5f * h) * (float)H_, H_);

        if (cf >= 0.3f && x2 > x1 && y2 > y1) {
            float area = (float)((y2 - y1) * (x2 - x1));
            int ys[4] = {y2, y1, y2, y1};
            int xs[4] = {x2, x2, x1, x1};
            const float sg[4] = {1.f, -1.f, -1.f, 1.f};
            float s = 0.0f;
            #pragma unroll
            for (int k = 0; k < 4; k++) {
                int yy = ys[k], xx = xs[k];
                if (yy > 0 && xx > 0) {
                    int c = (yy - 1) >> 3;
                    int x = xx - 1;
                    float v = g_corner[4 * i + k]
                            + g_agg[((size_t)(b * NCHUNK + c)) * W_ + x];
                    s += sg[k] * v;
                }
            }
            acc += (double)(fmaxf(s / area, 0.0f) * cf);
        }
    }

    __shared__ double sh[32];
    unsigned lane = t & 31, wid = t >> 5;
    #pragma unroll
    for (int o = 16; o > 0; o >>= 1)
        acc += __shfl_down_sync(0xFFFFFFFFu, acc, o);
    if (lane == 0) sh[wid] = acc;
    __syncthreads();
    if (wid == 0) {
        double v = sh[lane];
        #pragma unroll
        for (int o = 16; o > 0; o >>= 1)
            v += __shfl_down_sync(0xFFFFFFFFu, v, o);
        if (lane == 0) out[0] = (float)(v / (double)(B_ * N_));
    }
}

// ---------------------------------------------------------------------------
extern "C" void kernel_launch(void* const* d_in, const int* in_sizes, int n_in,
                              void* d_out, int out_size) {
    const float* det_boxes = (const float*)d_in[0];   // (32,300,4)
    const float* det_conf  = (const float*)d_in[1];   // (32,300)
    const float* seg_masks = (const float*)d_in[2];   // (32,3,1024,1024)
    float* out = (float*)d_out;

    bucketKernel<<<(B_ * N_ + 255) / 256, 256>>>(det_boxes, det_conf);
    scanChunk<<<TOTCHUNK, 256>>>(seg_masks);
    chunkScan<<<B_ * 32, 256>>>();
    boxKernel<<<1, 1024>>>(det_boxes, det_conf, out);
}

// round 11
// speedup vs baseline: 2.1694x; 1.1809x over previous
#include <cuda_runtime.h>
#include <cuda_bf16.h>

#define B_   32
#define N_   300
#define H_   1024
#define W_   1024
#define HW_  (1024 * 1024)
#define NCHUNK   128                 // row-chunks per batch (8 rows each)
#define TOTCHUNK (B_ * NCHUNK)       // 4096
#define SLOTS    256                 // edge chunks collect ~110 clamped corners; 256 is safe
#define NQ       (B_ * N_ * 4)       // 38400 corner slots
#define NB       (B_ * N_)           // 9600 boxes

// Fixed-point scale for the deterministic integer reduction.
// per_box <= 1, so sum < 9600 * 2^44 ~= 2^57.3 << 2^64. Quant err ~ 2^-44/item.
#define ACC_SCALE 17592186044416.0   // 2^44

// Scratch (static device arrays — no allocation). Zero-initialized at load.
__device__ float g_agg[(size_t)TOTCHUNK * W_];   // 16 MB: chunk column aggregates -> exclusive prefix
__device__ float g_corner[NQ];                   // chunk-local corner values
__device__ int   g_cnt[TOTCHUNK];
__device__ int   g_bucket[TOTCHUNK * SLOTS];
__device__ unsigned long long g_acc;             // fixed-point global accumulator

__device__ __forceinline__ int to_idx(float v, int m) {
    int i = (int)v;                  // trunc toward zero == jnp.trunc -> int32
    if (i < 0) i = 0;
    if (i > m - 1) i = m - 1;
    return i;
}

// ---------------------------------------------------------------------------
// K1: bucket corner queries by (batch, row-chunk). One thread per box.
// Packed entry: qid[0:17) | x[17:27) | r[27:30)
// Relies on g_cnt == 0 (zeroed at module load, re-zeroed by finalKernel).
// ---------------------------------------------------------------------------
__global__ void bucketKernel(const float* __restrict__ boxes,
                             const float* __restrict__ conf) {
    int i = blockIdx.x * blockDim.x + threadIdx.x;
    if (i >= NB) return;
    int b = i / N_;
    float4 bx = ((const float4*)boxes)[i];
    float cx = bx.x, cy = bx.y, w = bx.z, h = bx.w;
    float cf = conf[i];

    int x1 = to_idx((cx - 0.5f * w) * (float)W_, W_);
    int x2 = to_idx((cx + 0.5f * w) * (float)W_, W_);
    int y1 = to_idx((cy - 0.5f * h) * (float)H_, H_);
    int y2 = to_idx((cy + 0.5f * h) * (float)H_, H_);
    if (!(cf >= 0.3f && x2 > x1 && y2 > y1)) return;

    int ys[4] = {y2, y1, y2, y1};
    int xs[4] = {x2, x2, x1, x1};
    #pragma unroll
    for (int k = 0; k < 4; k++) {
        int yy = ys[k], xx = xs[k];
        if (yy > 0 && xx > 0) {
            int r = (yy - 1) & 7;
            int c = (yy - 1) >> 3;
            int chunk = b * NCHUNK + c;
            int x = xx - 1;
            int slot = atomicAdd(&g_cnt[chunk], 1);
            if (slot < SLOTS)
                g_bucket[chunk * SLOTS + slot] = (4 * i + k) | (x << 17) | (r << 27);
        }
    }
}

// ---------------------------------------------------------------------------
// K2: per-chunk local prefix. One block = one (b, 8-row chunk).
// ---------------------------------------------------------------------------
__global__ void __launch_bounds__(256) scanChunk(const float* __restrict__ seg) {
    __shared__ float sm[8 * W_];     // 32 KB: row-wise prefix sums
    int chunk = blockIdx.x;
    int b = chunk >> 7;
    int c = chunk & (NCHUNK - 1);
    int t = threadIdx.x;
    int lane = t & 31, wrow = t >> 5;
    int y = c * 8 + wrow;

    const float* p1 = seg + ((size_t)b * 3 + 1) * HW_ + (size_t)y * W_;
    const float* p2 = seg + ((size_t)b * 3 + 2) * HW_ + (size_t)y * W_;

    float carry = 0.0f;
    #pragma unroll
    for (int half = 0; half < 2; half++) {
        float4 d[4];
        #pragma unroll
        for (int i = 0; i < 4; i++) {
            int col = (half * 4 + i) * 128 + lane * 4;
            float4 a  = __ldcs((const float4*)(p1 + col));
            float4 bb = __ldcs((const float4*)(p2 + col));
            d[i] = make_float4(bb.x - a.x, bb.y - a.y, bb.z - a.z, bb.w - a.w);
        }
        #pragma unroll
        for (int i = 0; i < 4; i++) {
            float4 v = d[i];
            float s1 = v.x + v.y, s2 = s1 + v.z, s3 = s2 + v.w;
            float tot = s3;
            #pragma unroll
            for (int o = 1; o < 32; o <<= 1) {
                float n = __shfl_up_sync(0xFFFFFFFFu, tot, o);
                if (lane >= o) tot += n;
            }
            float excl = carry + (tot - s3);
            *(float4*)(&sm[wrow * W_ + (half * 4 + i) * 128 + lane * 4]) =
                make_float4(excl + v.x, excl + s1, excl + s2, excl + s3);
            carry += __shfl_sync(0xFFFFFFFFu, tot, 31);
        }
    }
    __syncthreads();

    // column aggregate over the 8 rows; registers only
    int x0 = t * 4;
    float4 acc = make_float4(0.f, 0.f, 0.f, 0.f);
    #pragma unroll
    for (int r = 0; r < 8; r++) {
        float4 v = *(float4*)(&sm[r * W_ + x0]);
        acc.x += v.x; acc.y += v.y; acc.z += v.z; acc.w += v.w;
    }
    *(float4*)(&g_agg[(size_t)chunk * W_ + x0]) = acc;

    // answer this chunk's queries: local ii(r,x) = sum_{r'<=r} rowprefix[r'][x]
    int cnt = g_cnt[chunk];
    if (cnt > SLOTS) cnt = SLOTS;
    for (int q = t; q < cnt; q += 256) {
        int e   = g_bucket[chunk * SLOTS + q];
        int qid = e & 0x1FFFF;
        int x   = (e >> 17) & 0x3FF;
        int r   = (e >> 27) & 7;
        float s = 0.0f;
        for (int rr = 0; rr <= r; rr++)
            s += sm[rr * W_ + x];
        g_corner[qid] = s;
    }
}

// ---------------------------------------------------------------------------
// K2b: in-place exclusive prefix of g_agg over 128 chunks per (b, column).
// ---------------------------------------------------------------------------
__global__ void __launch_bounds__(256) chunkScan() {
    __shared__ float sums[8][32];
    int blk  = blockIdx.x;            // 0..1023
    int b    = blk >> 5;
    int xg   = blk & 31;
    int lane = threadIdx.x & 31;
    int seg  = threadIdx.x >> 5;      // 16-chunk segment 0..7
    int x    = xg * 32 + lane;

    float* base = g_agg + (size_t)b * NCHUNK * W_ + x;

    float v[16];
    #pragma unroll
    for (int j = 0; j < 16; j++)
        v[j] = base[(size_t)(seg * 16 + j) * W_];

    float tot = 0.0f;
    #pragma unroll
    for (int j = 0; j < 16; j++) tot += v[j];

    sums[seg][lane] = tot;
    __syncthreads();

    float E = 0.0f;
    #pragma unroll
    for (int s = 0; s < 8; s++)
        if (s < seg) E += sums[s][lane];

    #pragma unroll
    for (int j = 0; j < 16; j++) {
        float tv = v[j];
        base[(size_t)(seg * 16 + j) * W_] = E;
        E += tv;
    }
}

// ---------------------------------------------------------------------------
// K3: per-box combine, grid-parallel. Deterministic via exact fixed-point
// integer atomics (order-independent). One thread per box.
// ---------------------------------------------------------------------------
__global__ void __launch_bounds__(256) boxKernel(const float* __restrict__ boxes,
                                                 const float* __restrict__ conf) {
    int i = blockIdx.x * blockDim.x + threadIdx.x;
    unsigned long long q = 0ull;

    if (i < NB) {
        int b = i / N_;
        float4 bx = ((const float4*)boxes)[i];
        float cx = bx.x, cy = bx.y, w = bx.z, h = bx.w;
        float cf = conf[i];

        int x1 = to_idx((cx - 0.5f * w) * (float)W_, W_);
        int x2 = to_idx((cx + 0.5f * w) * (float)W_, W_);
        int y1 = to_idx((cy - 0.5f * h) * (float)H_, H_);
        int y2 = to_idx((cy + 0.5f * h) * (float)H_, H_);

        if (cf >= 0.3f && x2 > x1 && y2 > y1) {
            float area = (float)((y2 - y1) * (x2 - x1));
            int ys[4] = {y2, y1, y2, y1};
            int xs[4] = {x2, x2, x1, x1};
            const float sg[4] = {1.f, -1.f, -1.f, 1.f};
            float s = 0.0f;
            #pragma unroll
            for (int k = 0; k < 4; k++) {
                int yy = ys[k], xx = xs[k];
                if (yy > 0 && xx > 0) {
                    int c = (yy - 1) >> 3;
                    int x = xx - 1;
                    float v = g_corner[4 * i + k]
                            + g_agg[((size_t)(b * NCHUNK + c)) * W_ + x];
                    s += sg[k] * v;
                }
            }
            double pb = (double)(fmaxf(s / area, 0.0f) * cf);
            q = (unsigned long long)(pb * ACC_SCALE + 0.5);   // exact quantize
        }
    }

    // exact integer warp reduction, one atomic per warp
    #pragma unroll
    for (int o = 16; o > 0; o >>= 1)
        q += __shfl_down_sync(0xFFFFFFFFu, q, o);
    if ((threadIdx.x & 31) == 0 && q)
        atomicAdd(&g_acc, q);
}

// ---------------------------------------------------------------------------
// K4: finalize + reset scratch state for the next (identical) graph replay.
// ---------------------------------------------------------------------------
__global__ void __launch_bounds__(1024) finalKernel(float* __restrict__ out) {
    int t = threadIdx.x;
    #pragma unroll
    for (int j = 0; j < TOTCHUNK / 1024; j++)
        g_cnt[j * 1024 + t] = 0;
    if (t == 0) {
        out[0] = (float)((double)g_acc / ACC_SCALE / (double)NB);
        g_acc = 0ull;
    }
}

// ---------------------------------------------------------------------------
extern "C" void kernel_launch(void* const* d_in, const int* in_sizes, int n_in,
                              void* d_out, int out_size) {
    const float* det_boxes = (const float*)d_in[0];   // (32,300,4)
    const float* det_conf  = (const float*)d_in[1];   // (32,300)
    const float* seg_masks = (const float*)d_in[2];   // (32,3,1024,1024)
    float* out = (float*)d_out;

    bucketKernel<<<(NB + 255) / 256, 256>>>(det_boxes, det_conf);
    scanChunk<<<TOTCHUNK, 256>>>(seg_masks);
    chunkScan<<<B_ * 32, 256>>>();
    boxKernel<<<(NB + 255) / 256, 256>>>(det_boxes, det_conf);
    finalKernel<<<1, 1024>>>(out);
}